// round 11
// baseline (speedup 1.0000x reference)
#include <cuda_runtime.h>
#include <cuda_bf16.h>

// CompactBilinearPooling: count-sketch into O=16384 buckets + circular conv
// via FFT. One CTA per batch row, 1024 threads, 16 elements per thread
// (doubled occupancy vs the 512-thread variant). Decomposition (all radix-4
// layers): A = radix-16 @ stride 1024, B = radix-16 @ stride 64 (within
// 1024-blocks), M = radix-4 @ L=16, D = 16 contiguous (radix-16) fused with
// the Hermitian pointwise product and the first inverse group in registers.
// XOR swizzle sw(i) = i ^ ((i>>4)&15) makes every phase bank-conflict-free.
// Twiddles: 1-2 smem loads per group, rest derived by immediate rotations.

#define N_FFT    16384
#define LOG2N    14
#define D_IN     4096
#define NTHREADS 1024
#define TW_N     4096

// packed fp32x2 add/sub (sm_103a)
__device__ __forceinline__ float2 cadd(float2 a, float2 b) {
    float2 r;
    asm("{\n\t.reg .b64 ra, rb, rc;\n\t"
        "mov.b64 ra, {%2,%3};\n\t"
        "mov.b64 rb, {%4,%5};\n\t"
        "add.rn.f32x2 rc, ra, rb;\n\t"
        "mov.b64 {%0,%1}, rc;\n\t}"
        : "=f"(r.x), "=f"(r.y)
        : "f"(a.x), "f"(a.y), "f"(b.x), "f"(b.y));
    return r;
}
__device__ __forceinline__ float2 csub(float2 a, float2 b) {
    float2 r;
    asm("{\n\t.reg .b64 ra, rb, rc;\n\t"
        "mov.b64 ra, {%2,%3};\n\t"
        "mov.b64 rb, {%4,%5};\n\t"
        "sub.rn.f32x2 rc, ra, rb;\n\t"
        "mov.b64 {%0,%1}, rc;\n\t}"
        : "=f"(r.x), "=f"(r.y)
        : "f"(a.x), "f"(a.y), "f"(b.x), "f"(b.y));
    return r;
}
__device__ __forceinline__ float2 cmul(float2 a, float2 b) {
    return make_float2(fmaf(a.x, b.x, -a.y * b.y),
                       fmaf(a.x, b.y,  a.y * b.x));
}
__device__ __forceinline__ float2 cconj(float2 a) {
    return make_float2(a.x, -a.y);
}
// w * (c + i s) with c, s immediates
__device__ __forceinline__ float2 twmul(float2 w, float c, float s) {
    return make_float2(fmaf(w.x, c, -w.y * s), fmaf(w.x, s, w.y * c));
}

// XOR bank swizzle: conflict-free for strides 1, 16, 64, 1024 access shapes
__device__ __forceinline__ int swz(int i) { return i ^ ((i >> 4) & 15); }

// base-4 digit reversal of 14-bit index (involution): pairswap(brev14(k))
__device__ __forceinline__ int dr14(int k) {
    unsigned r = __brev((unsigned)k) >> (32 - LOG2N);
    return (int)(((r & 0x1555u) << 1) | ((r >> 1) & 0x1555u));
}

// radix-4 DIF with all three twiddles given
__device__ __forceinline__ void dif_w(float2& a0, float2& a1, float2& a2,
                                      float2& a3, float2 w1, float2 w2,
                                      float2 w3) {
    float2 t0 = cadd(a0, a2), t1 = csub(a0, a2);
    float2 t2 = cadd(a1, a3), t3 = csub(a1, a3);
    float2 y0 = cadd(t0, t2);
    float2 y2 = csub(t0, t2);
    float2 y1 = make_float2(t1.x + t3.y, t1.y - t3.x);   // t1 - i*t3
    float2 y3 = make_float2(t1.x - t3.y, t1.y + t3.x);   // t1 + i*t3
    a0 = y0;
    a1 = cmul(y1, w1);
    a2 = cmul(y2, w2);
    a3 = cmul(y3, w3);
}
// radix-4 DIF, w == 1
__device__ __forceinline__ void dif_nt(float2& a0, float2& a1, float2& a2,
                                       float2& a3) {
    float2 t0 = cadd(a0, a2), t1 = csub(a0, a2);
    float2 t2 = cadd(a1, a3), t3 = csub(a1, a3);
    a0 = cadd(t0, t2);
    a2 = csub(t0, t2);
    a1 = make_float2(t1.x + t3.y, t1.y - t3.x);
    a3 = make_float2(t1.x - t3.y, t1.y + t3.x);
}
// radix-4 DIT with all three conj twiddles given
__device__ __forceinline__ void dit_w(float2& a0, float2& a1, float2& a2,
                                      float2& a3, float2 w1c, float2 w2c,
                                      float2 w3c) {
    float2 t1 = cmul(a1, w1c), t2 = cmul(a2, w2c), t3 = cmul(a3, w3c);
    float2 e0 = cadd(a0, t2), e1 = csub(a0, t2);
    float2 e2 = cadd(t1, t3), e3 = csub(t1, t3);
    a0 = cadd(e0, e2);
    a1 = make_float2(e1.x - e3.y, e1.y + e3.x);          // e1 + i*e3
    a2 = csub(e0, e2);
    a3 = make_float2(e1.x + e3.y, e1.y - e3.x);          // e1 - i*e3
}
// radix-4 DIT, w == 1
__device__ __forceinline__ void dit_nt(float2& a0, float2& a1, float2& a2,
                                       float2& a3) {
    float2 e0 = cadd(a0, a2), e1 = csub(a0, a2);
    float2 e2 = cadd(a1, a3), e3 = csub(a1, a3);
    a0 = cadd(e0, e2);
    a1 = make_float2(e1.x - e3.y, e1.y + e3.x);
    a2 = csub(e0, e2);
    a3 = make_float2(e1.x + e3.y, e1.y - e3.x);
}

// twiddle constants (16th roots)
#define C16A 0.92387953251128674f   // cos(pi/8)
#define S16A 0.38268343236508978f   // sin(pi/8)
#define RS2  0.70710678118654752f   // 1/sqrt(2)

// radix-16 DIF group on v[0..15] at uniform element stride; base twiddles
// w1 (layer 1) and w2 (layer 2); layer-1 step is e^{-i pi/8} per slot
// (element stride * 1 corresponds to twiddle index step 1024).
__device__ __forceinline__ void fwd16g(float2* v, float2 w1, float2 w2) {
    float2 w1s = cmul(w1, w1), w1t = cmul(w1s, w1);
    dif_w(v[0], v[4], v[8], v[12], w1, w1s, w1t);
    dif_w(v[1], v[5], v[9], v[13],
          twmul(w1, C16A, -S16A), twmul(w1s, RS2, -RS2),
          twmul(w1t, S16A, -C16A));
    dif_w(v[2], v[6], v[10], v[14],
          twmul(w1, RS2, -RS2), make_float2(w1s.y, -w1s.x),
          twmul(w1t, -RS2, -RS2));
    dif_w(v[3], v[7], v[11], v[15],
          twmul(w1, S16A, -C16A), twmul(w1s, -RS2, -RS2),
          twmul(w1t, -C16A, S16A));
    float2 w2s = cmul(w2, w2), w2t = cmul(w2s, w2);
    #pragma unroll
    for (int q = 0; q < 4; ++q)
        dif_w(v[4 * q], v[4 * q + 1], v[4 * q + 2], v[4 * q + 3],
              w2, w2s, w2t);
}
__device__ __forceinline__ void inv16g(float2* v, float2 w1c, float2 w2c) {
    float2 w2cs = cmul(w2c, w2c), w2ct = cmul(w2cs, w2c);
    #pragma unroll
    for (int q = 0; q < 4; ++q)
        dit_w(v[4 * q], v[4 * q + 1], v[4 * q + 2], v[4 * q + 3],
              w2c, w2cs, w2ct);
    float2 w1cs = cmul(w1c, w1c), w1ct = cmul(w1cs, w1c);
    dit_w(v[0], v[4], v[8], v[12], w1c, w1cs, w1ct);
    dit_w(v[1], v[5], v[9], v[13],
          twmul(w1c, C16A, S16A), twmul(w1cs, RS2, RS2),
          twmul(w1ct, S16A, C16A));
    dit_w(v[2], v[6], v[10], v[14],
          twmul(w1c, RS2, RS2), make_float2(-w1cs.y, w1cs.x),
          twmul(w1ct, -RS2, RS2));
    dit_w(v[3], v[7], v[11], v[15],
          twmul(w1c, S16A, C16A), twmul(w1cs, -RS2, RS2),
          twmul(w1ct, -C16A, -S16A));
}

// 16-point DIF/DIT on contiguous elements, all-immediate twiddles (w1=w2=1)
__device__ __forceinline__ void fwd16(float2* v) {
    dif_nt(v[0], v[4], v[8], v[12]);
    dif_w(v[1], v[5], v[9], v[13],
          make_float2( C16A, -S16A), make_float2( RS2, -RS2),
          make_float2( S16A, -C16A));
    dif_w(v[2], v[6], v[10], v[14],
          make_float2( RS2, -RS2), make_float2(0.0f, -1.0f),
          make_float2(-RS2, -RS2));
    dif_w(v[3], v[7], v[11], v[15],
          make_float2( S16A, -C16A), make_float2(-RS2, -RS2),
          make_float2(-C16A,  S16A));
    #pragma unroll
    for (int q = 0; q < 4; ++q)
        dif_nt(v[4 * q], v[4 * q + 1], v[4 * q + 2], v[4 * q + 3]);
}
__device__ __forceinline__ void inv16(float2* v) {
    #pragma unroll
    for (int q = 0; q < 4; ++q)
        dit_nt(v[4 * q], v[4 * q + 1], v[4 * q + 2], v[4 * q + 3]);
    dit_nt(v[0], v[4], v[8], v[12]);
    dit_w(v[1], v[5], v[9], v[13],
          make_float2( C16A,  S16A), make_float2( RS2,  RS2),
          make_float2( S16A,  C16A));
    dit_w(v[2], v[6], v[10], v[14],
          make_float2( RS2,  RS2), make_float2(0.0f, 1.0f),
          make_float2(-RS2,  RS2));
    dit_w(v[3], v[7], v[11], v[15],
          make_float2( S16A,  C16A), make_float2(-RS2,  RS2),
          make_float2(-C16A, -S16A));
}

__global__ __launch_bounds__(NTHREADS, 1)
void cbp_fft1k_kernel(const float* __restrict__ x1,
                      const float* __restrict__ x2,
                      const int*   __restrict__ h1,
                      const float* __restrict__ s1,
                      float*       __restrict__ out)
{
    extern __shared__ float2 smem[];
    float2* z  = smem;              // [N_FFT] swizzle-addressed work array
    float2* tw = smem + N_FFT;      // [TW_N] exp(-i*pi*k/8192), k < N/4
    float4* z4 = reinterpret_cast<float4*>(smem);

    const int tid = threadIdx.x;
    const int b   = blockIdx.x;

    // --- prefetch inputs (hide DRAM latency behind twiddle gen + zeroing) ---
    float4 pa1, pa2, pss;
    int4   phh;
    {
        const float4* x1v = reinterpret_cast<const float4*>(x1 + (size_t)b * D_IN);
        const float4* x2v = reinterpret_cast<const float4*>(x2 + (size_t)b * D_IN);
        pa1 = x1v[tid];
        pa2 = x2v[tid];
        phh = reinterpret_cast<const int4*>(h1)[tid];
        pss = reinterpret_cast<const float4*>(s1)[tid];
    }

    // --- twiddles: 1 sincospif/thread, rest derived by constant rotations ---
    {
        float s, c;
        sincospif(-(float)tid * (1.0f / 8192.0f), &s, &c);
        float2 w = make_float2(c, s);
        tw[tid]        = w;
        tw[tid + 1024] = twmul(w, C16A, -S16A);
        tw[tid + 2048] = twmul(w, RS2,  -RS2);
        tw[tid + 3072] = twmul(w, S16A, -C16A);
    }
    // --- zero the work array (float4 stores; swizzle is a bijection) ---
    #pragma unroll
    for (int it = 0; it < 8; ++it)
        z4[tid + it * NTHREADS] = make_float4(0.0f, 0.0f, 0.0f, 0.0f);
    __syncthreads();

    // --- count-sketch scatter from prefetched registers ---
    {
        int s0 = swz(phh.x), s1i = swz(phh.y);
        int s2 = swz(phh.z), s3 = swz(phh.w);
        atomicAdd(&z[s0].x,  pss.x * pa1.x);
        atomicAdd(&z[s0].y,  pss.x * pa2.x);
        atomicAdd(&z[s1i].x, pss.y * pa1.y);
        atomicAdd(&z[s1i].y, pss.y * pa2.y);
        atomicAdd(&z[s2].x,  pss.z * pa1.z);
        atomicAdd(&z[s2].y,  pss.z * pa2.z);
        atomicAdd(&z[s3].x,  pss.w * pa1.w);
        atomicAdd(&z[s3].y,  pss.w * pa2.w);
    }
    __syncthreads();

    float2 v[16];

    // ===== forward group A: radix-16, stride 1024 (layers L=4096, L=1024) =====
    // sw(np + 1024m) = sw(np) + 1024m (stride doesn't touch bits 4-7)
    {
        const int sA = swz(tid);
        #pragma unroll
        for (int m = 0; m < 16; ++m) v[m] = z[sA + 1024 * m];
        fwd16g(v, tw[tid], tw[4 * tid]);
        #pragma unroll
        for (int m = 0; m < 16; ++m) z[sA + 1024 * m] = v[m];
    }
    __syncthreads();

    // ===== forward group B: radix-16, stride 64 within 1024-blocks =====
    // (layers L=256, L=64); sw xor-const depends only on m&3
    {
        const int n6   = tid & 63;
        const int base = (tid >> 6) * 1024 + n6;
        const int xb   = n6 >> 4;
        #pragma unroll
        for (int m = 0; m < 16; ++m)
            v[m] = z[(base + 64 * m) ^ (xb + 4 * (m & 3))];
        fwd16g(v, tw[n6 << 4], tw[n6 << 6]);
        #pragma unroll
        for (int m = 0; m < 16; ++m)
            z[(base + 64 * m) ^ (xb + 4 * (m & 3))] = v[m];
    }
    __syncthreads();

    // ===== forward group M: single radix-4 layer, L=16 (within 64-blocks) ===
    // thread t: block = t>>2, butterflies n4 = (t&3) + 4u, u = 0..3
    {
        const int blk = tid >> 2;
        const int u0  = tid & 3;
        const int ib  = blk * 64 + u0;
        const int xm  = (blk << 2) & 15;
        #pragma unroll
        for (int u = 0; u < 4; ++u)
            #pragma unroll
            for (int c = 0; c < 4; ++c)
                v[4 * u + c] = z[(ib + 4 * u + 16 * c) ^ (xm | c)];
        float2 wm  = tw[u0 << 8];
        float2 wms = cmul(wm, wm), wmt = cmul(wms, wm);
        dif_w(v[0],  v[1],  v[2],  v[3],  wm, wms, wmt);
        dif_w(v[4],  v[5],  v[6],  v[7],
              twmul(wm, C16A, -S16A), twmul(wms, RS2, -RS2),
              twmul(wmt, S16A, -C16A));
        dif_w(v[8],  v[9],  v[10], v[11],
              twmul(wm, RS2, -RS2), make_float2(wms.y, -wms.x),
              twmul(wmt, -RS2, -RS2));
        dif_w(v[12], v[13], v[14], v[15],
              twmul(wm, S16A, -C16A), twmul(wms, -RS2, -RS2),
              twmul(wmt, -C16A, S16A));
        #pragma unroll
        for (int u = 0; u < 4; ++u)
            #pragma unroll
            for (int c = 0; c < 4; ++c)
                z[(ib + 4 * u + 16 * c) ^ (xm | c)] = v[4 * u + c];
    }
    // M -> D exchange is within-warp (D block 16t lies in 64-block t>>2,
    // written by threads (t & ~3)..(t & ~3)+3)
    __syncwarp();

    // ===== fused: group D (16 contiguous, layers L=4, L=1) -> pointwise ->
    //        inverse group D' =====
    {
        const int ib = 16 * tid;
        const int xc = tid & 15;
        #pragma unroll
        for (int m = 0; m < 16; ++m) v[m] = z[ib + (m ^ xc)];
        fwd16(v);
        // publish so other threads can read partners
        #pragma unroll
        for (int m = 0; m < 16; ++m) z[ib + (m ^ xc)] = v[m];
        __syncthreads();

        // Hermitian split + pointwise product (1/N folded into f2 scale).
        // Position j holds Z[k], k = dr14(j); partner holds Z[(N-k) mod N].
        // For khi = dr14(16t) != 0: partner(16t+m) = pb + (15-m),
        // pb = dr14(1024 - khi) (16-aligned block).
        const float CI = 0.5f / (float)N_FFT;   // exact power of 2
        if (tid != 0) {
            const int khi = dr14(ib);
            const int pb  = dr14(1024 - khi);
            const int xcp = (pb >> 4) & 15;
            #pragma unroll
            for (int m = 0; m < 16; ++m) {
                float2 A  = v[m];
                float2 Bv = z[pb + ((15 - m) ^ xcp)];
                float f1r = 0.5f * (A.x + Bv.x);
                float f1i = 0.5f * (A.y - Bv.y);
                float f2r = CI * (A.y + Bv.y);
                float f2i = CI * (Bv.x - A.x);
                v[m] = make_float2(f1r * f2r - f1i * f2i,
                                   f1r * f2i + f1i * f2r);
            }
        } else {
            // block 0 partners itself; general per-element path
            #pragma unroll
            for (int m = 0; m < 16; ++m) {
                int k  = dr14(m);
                int nk = (N_FFT - k) & (N_FFT - 1);
                int pj = dr14(nk);
                float2 A  = v[m];
                float2 Bv = z[swz(pj)];
                float f1r = 0.5f * (A.x + Bv.x);
                float f1i = 0.5f * (A.y - Bv.y);
                float f2r = CI * (A.y + Bv.y);
                float f2i = CI * (Bv.x - A.x);
                v[m] = make_float2(f1r * f2r - f1i * f2i,
                                   f1r * f2i + f1i * f2r);
            }
        }
        __syncthreads();   // all partner reads done before anyone overwrites z

        inv16(v);
        #pragma unroll
        for (int m = 0; m < 16; ++m) z[ib + (m ^ xc)] = v[m];
    }
    // D' -> M' exchange is within-warp (mirror of M -> D)
    __syncwarp();

    // ===== inverse group M' =====
    {
        const int blk = tid >> 2;
        const int u0  = tid & 3;
        const int ib  = blk * 64 + u0;
        const int xm  = (blk << 2) & 15;
        #pragma unroll
        for (int u = 0; u < 4; ++u)
            #pragma unroll
            for (int c = 0; c < 4; ++c)
                v[4 * u + c] = z[(ib + 4 * u + 16 * c) ^ (xm | c)];
        float2 wmc  = cconj(tw[u0 << 8]);
        float2 wmcs = cmul(wmc, wmc), wmct = cmul(wmcs, wmc);
        dit_w(v[0],  v[1],  v[2],  v[3],  wmc, wmcs, wmct);
        dit_w(v[4],  v[5],  v[6],  v[7],
              twmul(wmc, C16A, S16A), twmul(wmcs, RS2, RS2),
              twmul(wmct, S16A, C16A));
        dit_w(v[8],  v[9],  v[10], v[11],
              twmul(wmc, RS2, RS2), make_float2(-wmcs.y, wmcs.x),
              twmul(wmct, -RS2, RS2));
        dit_w(v[12], v[13], v[14], v[15],
              twmul(wmc, S16A, C16A), twmul(wmcs, -RS2, RS2),
              twmul(wmct, -C16A, -S16A));
        #pragma unroll
        for (int u = 0; u < 4; ++u)
            #pragma unroll
            for (int c = 0; c < 4; ++c)
                z[(ib + 4 * u + 16 * c) ^ (xm | c)] = v[4 * u + c];
    }
    __syncthreads();

    // ===== inverse group B' =====
    {
        const int n6   = tid & 63;
        const int base = (tid >> 6) * 1024 + n6;
        const int xb   = n6 >> 4;
        #pragma unroll
        for (int m = 0; m < 16; ++m)
            v[m] = z[(base + 64 * m) ^ (xb + 4 * (m & 3))];
        inv16g(v, cconj(tw[n6 << 4]), cconj(tw[n6 << 6]));
        #pragma unroll
        for (int m = 0; m < 16; ++m)
            z[(base + 64 * m) ^ (xb + 4 * (m & 3))] = v[m];
    }
    __syncthreads();

    // ===== inverse group A' + fused gmem epilogue =====
    {
        const int sA = swz(tid);
        #pragma unroll
        for (int m = 0; m < 16; ++m) v[m] = z[sA + 1024 * m];
        inv16g(v, cconj(tw[tid]), cconj(tw[4 * tid]));
        float* outr = out + (size_t)b * N_FFT;
        #pragma unroll
        for (int m = 0; m < 16; ++m)
            outr[tid + 1024 * m] = v[m].x;      // 1/N already folded in
    }
}

extern "C" void kernel_launch(void* const* d_in, const int* in_sizes, int n_in,
                              void* d_out, int out_size)
{
    const float* x1 = (const float*)d_in[0];
    const float* x2 = (const float*)d_in[1];
    const int*   h1 = (const int*)  d_in[2];
    const float* s1 = (const float*)d_in[3];
    float*       out = (float*)d_out;

    const int smem_bytes = (N_FFT + TW_N) * (int)sizeof(float2);  // 163840
    cudaFuncSetAttribute(cbp_fft1k_kernel,
                         cudaFuncAttributeMaxDynamicSharedMemorySize,
                         smem_bytes);

    const int batch = out_size / N_FFT;   // 256
    cbp_fft1k_kernel<<<batch, NTHREADS, smem_bytes>>>(x1, x2, h1, s1, out);
}

// round 12
// speedup vs baseline: 1.1655x; 1.1655x over previous
#include <cuda_runtime.h>
#include <cuda_bf16.h>

// CompactBilinearPooling: count-sketch into O=16384 buckets + circular conv
// via FFT. Persistent CTAs: grid = B/2, each CTA processes two batch rows
// (b and b+gridDim.x) with the twiddle table built once. Per row: 512
// threads, 32 elements per thread; radix-32 (stride 512), radix-32 (stride
// 16), radix-16 (contig) DIF groups; twiddle powers derived by immediate
// rotations (3 smem twiddle loads per strided group); Hermitian pointwise
// product fused with the last forward + first inverse group in registers;
// closed-form partner indexing; 1/N folded into the pointwise constants.

#define N_FFT    16384
#define LOG2N    14
#define D_IN     4096
#define NTHREADS 512
#define TW_N     4096
#define Z_SLOTS  17408   // slot(16383)=16383+2*511=17405, rounded to /4

__device__ __forceinline__ int slotof(int i) { return i + 2 * (i >> 5); }

// packed fp32x2 add/sub (sm_103a)
__device__ __forceinline__ float2 cadd(float2 a, float2 b) {
    float2 r;
    asm("{\n\t.reg .b64 ra, rb, rc;\n\t"
        "mov.b64 ra, {%2,%3};\n\t"
        "mov.b64 rb, {%4,%5};\n\t"
        "add.rn.f32x2 rc, ra, rb;\n\t"
        "mov.b64 {%0,%1}, rc;\n\t}"
        : "=f"(r.x), "=f"(r.y)
        : "f"(a.x), "f"(a.y), "f"(b.x), "f"(b.y));
    return r;
}
__device__ __forceinline__ float2 csub(float2 a, float2 b) {
    float2 r;
    asm("{\n\t.reg .b64 ra, rb, rc;\n\t"
        "mov.b64 ra, {%2,%3};\n\t"
        "mov.b64 rb, {%4,%5};\n\t"
        "sub.rn.f32x2 rc, ra, rb;\n\t"
        "mov.b64 {%0,%1}, rc;\n\t}"
        : "=f"(r.x), "=f"(r.y)
        : "f"(a.x), "f"(a.y), "f"(b.x), "f"(b.y));
    return r;
}
__device__ __forceinline__ float2 cmul(float2 a, float2 b) {
    return make_float2(fmaf(a.x, b.x, -a.y * b.y),
                       fmaf(a.x, b.y,  a.y * b.x));
}
__device__ __forceinline__ float2 cconj(float2 a) {
    return make_float2(a.x, -a.y);
}
// w * (c + i s) with c, s immediates
__device__ __forceinline__ float2 twmul(float2 w, float c, float s) {
    return make_float2(fmaf(w.x, c, -w.y * s), fmaf(w.x, s, w.y * c));
}

// twiddle fetch for indices in [0, 8192): table holds k < 4096;
// w^(4096+r) = -i * w^r = (s, -c)
__device__ __forceinline__ float2 twr2(const float2* tw, int idx) {
    float2 t = tw[idx & (TW_N - 1)];
    return (idx & TW_N) ? make_float2(t.y, -t.x) : t;
}

// position <-> frequency involution for digit pattern [2,2,1,2,2,1,2,2]:
// 14-bit reverse, then swap adjacent bit pairs at {0,2,5,7,10,12}; bits 4,9 fixed.
__device__ __forceinline__ int rho(int j) {
    unsigned b = __brev((unsigned)j) >> (32 - LOG2N);
    return (int)(((b & 0x14A5u) << 1) | ((b >> 1) & 0x14A5u) | (b & 0x0210u));
}

// radix-4 DIF with all three twiddles given
__device__ __forceinline__ void dif_w(float2& a0, float2& a1, float2& a2,
                                      float2& a3, float2 w1, float2 w2,
                                      float2 w3) {
    float2 t0 = cadd(a0, a2), t1 = csub(a0, a2);
    float2 t2 = cadd(a1, a3), t3 = csub(a1, a3);
    float2 y0 = cadd(t0, t2);
    float2 y2 = csub(t0, t2);
    float2 y1 = make_float2(t1.x + t3.y, t1.y - t3.x);   // t1 - i*t3
    float2 y3 = make_float2(t1.x - t3.y, t1.y + t3.x);   // t1 + i*t3
    a0 = y0;
    a1 = cmul(y1, w1);
    a2 = cmul(y2, w2);
    a3 = cmul(y3, w3);
}
// radix-4 DIF, w == 1
__device__ __forceinline__ void dif_nt(float2& a0, float2& a1, float2& a2,
                                       float2& a3) {
    float2 t0 = cadd(a0, a2), t1 = csub(a0, a2);
    float2 t2 = cadd(a1, a3), t3 = csub(a1, a3);
    a0 = cadd(t0, t2);
    a2 = csub(t0, t2);
    a1 = make_float2(t1.x + t3.y, t1.y - t3.x);
    a3 = make_float2(t1.x - t3.y, t1.y + t3.x);
}
// radix-4 DIT with all three conj twiddles given
__device__ __forceinline__ void dit_w(float2& a0, float2& a1, float2& a2,
                                      float2& a3, float2 w1c, float2 w2c,
                                      float2 w3c) {
    float2 t1 = cmul(a1, w1c), t2 = cmul(a2, w2c), t3 = cmul(a3, w3c);
    float2 e0 = cadd(a0, t2), e1 = csub(a0, t2);
    float2 e2 = cadd(t1, t3), e3 = csub(t1, t3);
    a0 = cadd(e0, e2);
    a1 = make_float2(e1.x - e3.y, e1.y + e3.x);          // e1 + i*e3
    a2 = csub(e0, e2);
    a3 = make_float2(e1.x + e3.y, e1.y - e3.x);          // e1 - i*e3
}
// radix-4 DIT, w == 1
__device__ __forceinline__ void dit_nt(float2& a0, float2& a1, float2& a2,
                                       float2& a3) {
    float2 e0 = cadd(a0, a2), e1 = csub(a0, a2);
    float2 e2 = cadd(a1, a3), e3 = csub(a1, a3);
    a0 = cadd(e0, e2);
    a1 = make_float2(e1.x - e3.y, e1.y + e3.x);
    a2 = csub(e0, e2);
    a3 = make_float2(e1.x + e3.y, e1.y - e3.x);
}

// radix-2 DIF: a'=a+b, b'=(a-b)w
__device__ __forceinline__ void dif2(float2& a, float2& b, float2 w) {
    float2 s = cadd(a, b), d = csub(a, b);
    a = s;
    b = cmul(d, w);
}
// radix-2 DIT: t=b*wc; a'=a+t, b'=a-t
__device__ __forceinline__ void dit2(float2& a, float2& b, float2 wc) {
    float2 t = cmul(b, wc);
    b = csub(a, t);
    a = cadd(a, t);
}

// twiddle constants
#define C16A 0.92387953251128674f   // cos(pi/8)
#define S16A 0.38268343236508978f   // sin(pi/8)
#define RS2  0.70710678118654752f   // 1/sqrt(2)
#define C32A 0.98078528040323044f   // cos(pi/16)
#define S32A 0.19509032201612827f   // sin(pi/16)
#define C32B 0.83146961230254524f   // cos(3pi/16)
#define S32B 0.55557023301960218f   // sin(3pi/16)

// 32-point DIF on v[0..31]; base twiddles w1=tw[n], w2=tw[4n], wr=tw[16n].
__device__ __forceinline__ void fwd32(float2* v, float2 w1, float2 w2,
                                      float2 wr) {
    float2 w1s = cmul(w1, w1), w1t = cmul(w1s, w1);
    dif_w(v[0], v[8], v[16], v[24], w1, w1s, w1t);
    dif_w(v[1], v[9], v[17], v[25],
          twmul(w1, C32A, -S32A), twmul(w1s, C16A, -S16A),
          twmul(w1t, C32B, -S32B));
    dif_w(v[2], v[10], v[18], v[26],
          twmul(w1, C16A, -S16A), twmul(w1s, RS2, -RS2),
          twmul(w1t, S16A, -C16A));
    dif_w(v[3], v[11], v[19], v[27],
          twmul(w1, C32B, -S32B), twmul(w1s, S16A, -C16A),
          twmul(w1t, -S32A, -C32A));
    dif_w(v[4], v[12], v[20], v[28],
          twmul(w1, RS2, -RS2), twmul(w1s, 0.0f, -1.0f),
          twmul(w1t, -RS2, -RS2));
    dif_w(v[5], v[13], v[21], v[29],
          twmul(w1, S32B, -C32B), twmul(w1s, -S16A, -C16A),
          twmul(w1t, -C32A, -S32A));
    dif_w(v[6], v[14], v[22], v[30],
          twmul(w1, S16A, -C16A), twmul(w1s, -RS2, -RS2),
          twmul(w1t, -C16A, S16A));
    dif_w(v[7], v[15], v[23], v[31],
          twmul(w1, S32A, -C32A), twmul(w1s, -C16A, -S16A),
          twmul(w1t, -S32B, C32B));
    float2 w2s = cmul(w2, w2), w2t = cmul(w2s, w2);
    float2 w2b  = twmul(w2, RS2, -RS2);
    float2 w2bs = make_float2(w2s.y, -w2s.x);       // w2s * (0,-1)
    float2 w2bt = twmul(w2t, -RS2, -RS2);
    #pragma unroll
    for (int mb = 0; mb < 32; mb += 8) {
        dif_w(v[mb],     v[mb + 2], v[mb + 4], v[mb + 6], w2, w2s, w2t);
        dif_w(v[mb + 1], v[mb + 3], v[mb + 5], v[mb + 7], w2b, w2bs, w2bt);
    }
    #pragma unroll
    for (int m = 0; m < 32; m += 2) dif2(v[m], v[m + 1], wr);
}
// inverse: base twiddles already conjugated; constants conjugated
__device__ __forceinline__ void inv32(float2* v, float2 w1c, float2 w2c,
                                      float2 wrc) {
    #pragma unroll
    for (int m = 0; m < 32; m += 2) dit2(v[m], v[m + 1], wrc);
    float2 w2cs = cmul(w2c, w2c), w2ct = cmul(w2cs, w2c);
    float2 w2bc  = twmul(w2c, RS2, RS2);
    float2 w2bcs = make_float2(-w2cs.y, w2cs.x);    // w2cs * (0,+1)
    float2 w2bct = twmul(w2ct, -RS2, RS2);
    #pragma unroll
    for (int mb = 0; mb < 32; mb += 8) {
        dit_w(v[mb],     v[mb + 2], v[mb + 4], v[mb + 6], w2c, w2cs, w2ct);
        dit_w(v[mb + 1], v[mb + 3], v[mb + 5], v[mb + 7], w2bc, w2bcs, w2bct);
    }
    float2 w1cs = cmul(w1c, w1c), w1ct = cmul(w1cs, w1c);
    dit_w(v[0], v[8], v[16], v[24], w1c, w1cs, w1ct);
    dit_w(v[1], v[9], v[17], v[25],
          twmul(w1c, C32A, S32A), twmul(w1cs, C16A, S16A),
          twmul(w1ct, C32B, S32B));
    dit_w(v[2], v[10], v[18], v[26],
          twmul(w1c, C16A, S16A), twmul(w1cs, RS2, RS2),
          twmul(w1ct, S16A, C16A));
    dit_w(v[3], v[11], v[19], v[27],
          twmul(w1c, C32B, S32B), twmul(w1cs, S16A, C16A),
          twmul(w1ct, -S32A, C32A));
    dit_w(v[4], v[12], v[20], v[28],
          twmul(w1c, RS2, RS2), twmul(w1cs, 0.0f, 1.0f),
          twmul(w1ct, -RS2, RS2));
    dit_w(v[5], v[13], v[21], v[29],
          twmul(w1c, S32B, C32B), twmul(w1cs, -S16A, C16A),
          twmul(w1ct, -C32A, S32A));
    dit_w(v[6], v[14], v[22], v[30],
          twmul(w1c, S16A, C16A), twmul(w1cs, -RS2, RS2),
          twmul(w1ct, -C16A, -S16A));
    dit_w(v[7], v[15], v[23], v[31],
          twmul(w1c, S32A, C32A), twmul(w1cs, -C16A, S16A),
          twmul(w1ct, -S32B, -C32B));
}

// 16-point DIF/DIT on contiguous register elements, all-immediate twiddles
__device__ __forceinline__ void fwd16(float2* v) {
    dif_nt(v[0], v[4], v[8], v[12]);
    dif_w(v[1], v[5], v[9], v[13],
          make_float2( C16A, -S16A), make_float2( RS2, -RS2),
          make_float2( S16A, -C16A));
    dif_w(v[2], v[6], v[10], v[14],
          make_float2( RS2, -RS2), make_float2(0.0f, -1.0f),
          make_float2(-RS2, -RS2));
    dif_w(v[3], v[7], v[11], v[15],
          make_float2( S16A, -C16A), make_float2(-RS2, -RS2),
          make_float2(-C16A,  S16A));
    #pragma unroll
    for (int q = 0; q < 4; ++q)
        dif_nt(v[4 * q], v[4 * q + 1], v[4 * q + 2], v[4 * q + 3]);
}
__device__ __forceinline__ void inv16(float2* v) {
    #pragma unroll
    for (int q = 0; q < 4; ++q)
        dit_nt(v[4 * q], v[4 * q + 1], v[4 * q + 2], v[4 * q + 3]);
    dit_nt(v[0], v[4], v[8], v[12]);
    dit_w(v[1], v[5], v[9], v[13],
          make_float2( C16A,  S16A), make_float2( RS2,  RS2),
          make_float2( S16A,  C16A));
    dit_w(v[2], v[6], v[10], v[14],
          make_float2( RS2,  RS2), make_float2(0.0f, 1.0f),
          make_float2(-RS2,  RS2));
    dit_w(v[3], v[7], v[11], v[15],
          make_float2( S16A,  C16A), make_float2(-RS2,  RS2),
          make_float2(-C16A, -S16A));
}

__global__ __launch_bounds__(NTHREADS, 1)
void cbp_fft32p_kernel(const float* __restrict__ x1,
                       const float* __restrict__ x2,
                       const int*   __restrict__ h1,
                       const float* __restrict__ s1,
                       float*       __restrict__ out,
                       int rows_per_cta)
{
    extern __shared__ float2 smem[];
    float2* z  = smem;              // padded work array
    float2* tw = smem + Z_SLOTS;    // [TW_N] exp(-i*pi*k/8192), k < N/4
    float4* z4 = reinterpret_cast<float4*>(smem);

    const int tid = threadIdx.x;

    // --- twiddles built ONCE: 2 sincospif, rest by constant rotations ---
    {
        const float2 cA = make_float2(C16A, -S16A);
        const float2 cB = make_float2(RS2,  -RS2);
        const float2 cC = make_float2(S16A, -C16A);
        #pragma unroll
        for (int it = 0; it < 2; ++it) {
            int k = tid + it * NTHREADS;     // k < 1024
            float s, c;
            sincospif(-(float)k * (1.0f / 8192.0f), &s, &c);
            float2 w = make_float2(c, s);
            tw[k]        = w;
            tw[k + 1024] = cmul(w, cA);
            tw[k + 2048] = cmul(w, cB);
            tw[k + 3072] = cmul(w, cC);
        }
    }

    #pragma unroll 1
    for (int r = 0; r < rows_per_cta; ++r) {
        const int b = blockIdx.x + r * gridDim.x;

        // barrier: row r-1 epilogue z-reads (and twiddle writes on r=0)
        // must complete before zeroing
        __syncthreads();

        // --- prefetch inputs (hidden behind zeroing) ---
        float4 pa1[2], pa2[2], pss[2];
        int4   phh[2];
        {
            const float4* x1v = reinterpret_cast<const float4*>(x1 + (size_t)b * D_IN);
            const float4* x2v = reinterpret_cast<const float4*>(x2 + (size_t)b * D_IN);
            const int4*   h1v = reinterpret_cast<const int4*>(h1);
            const float4* s1v = reinterpret_cast<const float4*>(s1);
            #pragma unroll
            for (int it = 0; it < 2; ++it) {
                int idx = tid + it * NTHREADS;
                pa1[it] = x1v[idx];
                pa2[it] = x2v[idx];
                phh[it] = h1v[idx];
                pss[it] = s1v[idx];
            }
        }

        // --- zero the padded work array (float4 stores) ---
        #pragma unroll
        for (int i = tid; i < Z_SLOTS / 2; i += NTHREADS)
            z4[i] = make_float4(0.0f, 0.0f, 0.0f, 0.0f);
        __syncthreads();

        // --- count-sketch scatter from prefetched registers ---
        #pragma unroll
        for (int it = 0; it < 2; ++it) {
            float4 a1 = pa1[it];
            float4 a2 = pa2[it];
            int4   hh = phh[it];
            float4 ss = pss[it];
            int s0 = slotof(hh.x), s1i = slotof(hh.y);
            int s2 = slotof(hh.z), s3 = slotof(hh.w);
            atomicAdd(&z[s0].x,  ss.x * a1.x);
            atomicAdd(&z[s0].y,  ss.x * a2.x);
            atomicAdd(&z[s1i].x, ss.y * a1.y);
            atomicAdd(&z[s1i].y, ss.y * a2.y);
            atomicAdd(&z[s2].x,  ss.z * a1.z);
            atomicAdd(&z[s2].y,  ss.z * a2.z);
            atomicAdd(&z[s3].x,  ss.w * a1.w);
            atomicAdd(&z[s3].y,  ss.w * a2.w);
        }
        __syncthreads();

        float2 v[32];

        // ============ forward group A: 5 bits, stride 512 ============
        {
            const int np = tid;
            #pragma unroll
            for (int m = 0; m < 32; ++m) v[m] = z[slotof(np + m * 512)];
            fwd32(v, tw[np], tw[np << 2], twr2(tw, np << 4));
            #pragma unroll
            for (int m = 0; m < 32; ++m) z[slotof(np + m * 512)] = v[m];
        }
        __syncthreads();

        // ========= forward group B: 5 bits, stride 16 in 512-blocks =======
        {
            const int lane = tid & 15;
            const int base = (tid >> 4) * 512 + lane;
            #pragma unroll
            for (int m = 0; m < 32; ++m) v[m] = z[slotof(base + m * 16)];
            fwd32(v, tw[lane << 5], tw[lane << 7], twr2(tw, lane << 9));
            #pragma unroll
            for (int m = 0; m < 32; ++m) z[slotof(base + m * 16)] = v[m];
        }
        // exchange with group C is confined to 16 threads of the same warp
        __syncwarp();

        // ==== fused: group C (two 16-pt FFTs) -> pointwise -> group C' ====
        {
            const int f4base = 17 * tid;     // float4 index of own block
            #pragma unroll
            for (int j = 0; j < 16; ++j) {
                float4 q = z4[f4base + j];
                v[2 * j]     = make_float2(q.x, q.y);
                v[2 * j + 1] = make_float2(q.z, q.w);
            }
            fwd16(v);
            fwd16(v + 16);
            #pragma unroll
            for (int j = 0; j < 16; ++j)
                z4[f4base + j] = make_float4(v[2 * j].x, v[2 * j].y,
                                             v[2 * j + 1].x, v[2 * j + 1].y);
            __syncthreads();

            // Hermitian split + pointwise product (1/N folded into f2 scale)
            const float CI = 0.5f / (float)N_FFT;   // exact power of 2
            if (tid != 0) {
                const int khi = rho(32 * tid);
                const int pb  = rho(512 - khi);        // 32-aligned block
                const int pf4 = 17 * (pb >> 5);
                #pragma unroll
                for (int jj = 0; jj < 16; ++jj) {
                    float4 pq = z4[pf4 + 15 - jj];
                    float2 A0 = v[2 * jj];
                    float2 B0 = make_float2(pq.z, pq.w);
                    float2 A1 = v[2 * jj + 1];
                    float2 B1 = make_float2(pq.x, pq.y);
                    {
                        float f1r = 0.5f * (A0.x + B0.x);
                        float f1i = 0.5f * (A0.y - B0.y);
                        float f2r = CI * (A0.y + B0.y);
                        float f2i = CI * (B0.x - A0.x);
                        v[2 * jj] = make_float2(f1r * f2r - f1i * f2i,
                                                f1r * f2i + f1i * f2r);
                    }
                    {
                        float f1r = 0.5f * (A1.x + B1.x);
                        float f1i = 0.5f * (A1.y - B1.y);
                        float f2r = CI * (A1.y + B1.y);
                        float f2i = CI * (B1.x - A1.x);
                        v[2 * jj + 1] = make_float2(f1r * f2r - f1i * f2i,
                                                    f1r * f2i + f1i * f2r);
                    }
                }
            } else {
                #pragma unroll
                for (int m = 0; m < 32; ++m) {
                    int k  = rho(m);
                    int nk = (N_FFT - k) & (N_FFT - 1);
                    int pj = rho(nk);
                    float2 A  = v[m];
                    float2 Bv = z[slotof(pj)];
                    float f1r = 0.5f * (A.x + Bv.x);
                    float f1i = 0.5f * (A.y - Bv.y);
                    float f2r = CI * (A.y + Bv.y);
                    float f2i = CI * (Bv.x - A.x);
                    v[m] = make_float2(f1r * f2r - f1i * f2i,
                                       f1r * f2i + f1i * f2r);
                }
            }
            __syncthreads();   // partner reads done before overwriting z

            inv16(v);
            inv16(v + 16);
            #pragma unroll
            for (int j = 0; j < 16; ++j)
                z4[f4base + j] = make_float4(v[2 * j].x, v[2 * j].y,
                                             v[2 * j + 1].x, v[2 * j + 1].y);
        }
        // exchange with group B' is warp-local
        __syncwarp();

        // ============ inverse group B' ============
        {
            const int lane = tid & 15;
            const int base = (tid >> 4) * 512 + lane;
            #pragma unroll
            for (int m = 0; m < 32; ++m) v[m] = z[slotof(base + m * 16)];
            inv32(v, cconj(tw[lane << 5]), cconj(tw[lane << 7]),
                  cconj(twr2(tw, lane << 9)));
            #pragma unroll
            for (int m = 0; m < 32; ++m) z[slotof(base + m * 16)] = v[m];
        }
        __syncthreads();

        // ============ inverse group A' + fused gmem epilogue ============
        {
            const int np = tid;
            #pragma unroll
            for (int m = 0; m < 32; ++m) v[m] = z[slotof(np + m * 512)];
            inv32(v, cconj(tw[np]), cconj(tw[np << 2]),
                  cconj(twr2(tw, np << 4)));
            float* outr = out + (size_t)b * N_FFT;
            #pragma unroll
            for (int m = 0; m < 32; ++m)
                outr[np + m * 512] = v[m].x;    // 1/N already folded in
        }
    }
}

extern "C" void kernel_launch(void* const* d_in, const int* in_sizes, int n_in,
                              void* d_out, int out_size)
{
    const float* x1 = (const float*)d_in[0];
    const float* x2 = (const float*)d_in[1];
    const int*   h1 = (const int*)  d_in[2];
    const float* s1 = (const float*)d_in[3];
    float*       out = (float*)d_out;

    const int smem_bytes = (Z_SLOTS + TW_N) * (int)sizeof(float2);  // 172032
    cudaFuncSetAttribute(cbp_fft32p_kernel,
                         cudaFuncAttributeMaxDynamicSharedMemorySize,
                         smem_bytes);

    const int batch = out_size / N_FFT;   // 256
    const int rows_per_cta = 2;
    const int grid = batch / rows_per_cta;  // 128 CTAs -> one balanced wave
    cbp_fft32p_kernel<<<grid, NTHREADS, smem_bytes>>>(x1, x2, h1, s1, out,
                                                      rows_per_cta);
}